// round 6
// baseline (speedup 1.0000x reference)
#include <cuda_runtime.h>
#include <math_constants.h>

// Fixed problem shape: [16, 17, 384, 384] fp32
#define HM_W 384
#define HM_H 384
#define HM_PLANES 272
#define BAND 32
#define BANDS (HM_H / BAND)          // 12
#define WARPS 4
#define TPB (WARPS * 32)             // 128
#define NUNITS (HM_PLANES * BANDS)   // 3264
#define NBLOCKS (NUNITS / WARPS)     // 816

#define SIG_THRESH 0.05f
#define FULLM 0xffffffffu

__device__ __forceinline__ float max3(float a, float b, float c) {
    return fmaxf(a, fmaxf(b, c));
}

__device__ __forceinline__ float4 max3v(const float4& a, const float4& b, const float4& c) {
    float4 r;
    r.x = max3(a.x, b.x, c.x);
    r.y = max3(a.y, b.y, c.y);
    r.z = max3(a.z, b.z, c.z);
    r.w = max3(a.w, b.w, c.w);
    return r;
}

// peak score: sigmoid(x) if (3x3 max == x) && sigmoid(x) > 0.05, else 0
__device__ __forceinline__ float peak(float m, float x) {
    float e = __expf(-x);
    float s = __fdividef(1.0f, 1.0f + e);
    return (m == x && s > SIG_THRESH) ? s : 0.0f;
}

__device__ __forceinline__ float4 peaks4(const float4& c, const float4& v,
                                         float vl, float vr) {
    float4 r;
    r.x = peak(max3(vl,  v.x, v.y), c.x);
    r.y = peak(max3(v.x, v.y, v.z), c.y);
    r.z = peak(max3(v.y, v.z, v.w), c.z);
    r.w = peak(max3(v.z, v.w, vr),  c.w);
    return r;
}

__global__ __launch_bounds__(TPB, 5)
void heatmap_peaks_kernel(const float* __restrict__ in, float* __restrict__ out) {
    const int lane = threadIdx.x & 31;
    const int warp = threadIdx.x >> 5;
    const int unit = blockIdx.x * WARPS + warp;

    const int plane = unit / BANDS;
    const int band  = unit - plane * BANDS;

    const float* __restrict__ p = in  + (size_t)plane * (HM_W * HM_H);
    float* __restrict__       o = out + (size_t)plane * (HM_W * HM_H);

    const int r0 = band * BAND;
    const int xb = lane * 4;           // interleaved: cols xb, xb+128, xb+256
    const float NEG = -CUDART_INF_F;
    const float4 NEG4 = make_float4(NEG, NEG, NEG, NEG);

    // Carried rows: P=r-1, C=r, N=r+1, plus L=r+2 prefetch.
    float4 P0, P1, P2, C0, C1, C2, N0, N1, N2;

    if (r0 > 0) {
        const float* rp = p + (size_t)(r0 - 1) * HM_W + xb;
        P0 = *(const float4*)(rp);
        P1 = *(const float4*)(rp + 128);
        P2 = *(const float4*)(rp + 256);
    } else {
        P0 = NEG4; P1 = NEG4; P2 = NEG4;
    }
    {
        const float* rp = p + (size_t)r0 * HM_W + xb;
        C0 = *(const float4*)(rp);
        C1 = *(const float4*)(rp + 128);
        C2 = *(const float4*)(rp + 256);
    }
    {   // row r0+1 always exists (r0 <= 352)
        const float* rp = p + (size_t)(r0 + 1) * HM_W + xb;
        N0 = *(const float4*)(rp);
        N1 = *(const float4*)(rp + 128);
        N2 = *(const float4*)(rp + 256);
    }

    const float* lp = p + (size_t)(r0 + 2) * HM_W + xb;   // prefetch ptr (row r+2)
    float*       op = o + (size_t)r0 * HM_W + xb;         // output ptr (row r)
    const int last_load = (r0 + BAND < HM_H) ? (r0 + BAND) : (HM_H - 1);

    #pragma unroll 4
    for (int r = r0; r < r0 + BAND; ++r) {
        // Prefetch row r+2 (consumed next iteration), clamped to band halo.
        float4 L0, L1, L2;
        if (r + 2 <= last_load) {
            L0 = *(const float4*)(lp);
            L1 = *(const float4*)(lp + 128);
            L2 = *(const float4*)(lp + 256);
        } else {
            L0 = NEG4; L1 = NEG4; L2 = NEG4;
        }
        lp += HM_W;

        // Vertical 3-max per column (component-wise)
        float4 v0 = max3v(P0, C0, N0);
        float4 v1 = max3v(P1, C1, N1);
        float4 v2 = max3v(P2, C2, N2);

        // Horizontal neighbors via warp shuffles (R2 scheme).
        float l0 = __shfl_up_sync(FULLM, v0.w, 1);
        float l1 = __shfl_up_sync(FULLM, v1.w, 1);
        float l2 = __shfl_up_sync(FULLM, v2.w, 1);
        float b01 = __shfl_sync(FULLM, v0.w, 31);
        float b12 = __shfl_sync(FULLM, v1.w, 31);
        float r0s = __shfl_down_sync(FULLM, v0.x, 1);
        float r1s = __shfl_down_sync(FULLM, v1.x, 1);
        float r2s = __shfl_down_sync(FULLM, v2.x, 1);
        float f10 = __shfl_sync(FULLM, v1.x, 0);
        float f21 = __shfl_sync(FULLM, v2.x, 0);

        if (lane == 0)  { l0 = NEG; l1 = b01; l2 = b12; }
        if (lane == 31) { r0s = f10; r1s = f21; r2s = NEG; }

        // Peak test + sigmoid, store row (plain stores — no asm barriers)
        float4 o0 = peaks4(C0, v0, l0, r0s);
        float4 o1 = peaks4(C1, v1, l1, r1s);
        float4 o2 = peaks4(C2, v2, l2, r2s);

        *(float4*)(op)       = o0;
        *(float4*)(op + 128) = o1;
        *(float4*)(op + 256) = o2;
        op += HM_W;

        // Rotate carried rows
        P0 = C0; P1 = C1; P2 = C2;
        C0 = N0; C1 = N1; C2 = N2;
        N0 = L0; N1 = L1; N2 = L2;
    }
}

extern "C" void kernel_launch(void* const* d_in, const int* in_sizes, int n_in,
                              void* d_out, int out_size) {
    (void)in_sizes; (void)n_in; (void)out_size;
    const float* heatmaps = (const float*)d_in[0];
    float* out = (float*)d_out;

    heatmap_peaks_kernel<<<NBLOCKS, TPB>>>(heatmaps, out);
}

// round 7
// speedup vs baseline: 1.1803x; 1.1803x over previous
#include <cuda_runtime.h>
#include <math_constants.h>

// Fixed problem shape: [16, 17, 384, 384] fp32
#define HM_W 384
#define HM_H 384
#define HM_PLANES 272
#define BAND 32
#define BANDS (HM_H / BAND)          // 12
#define WARPS 2
#define TPB (WARPS * 32)             // 64
#define NUNITS (HM_PLANES * BANDS)   // 3264
#define NBLOCKS (NUNITS / WARPS)     // 1632  (~11.03 blocks/SM: balanced single wave)

#define SIG_THRESH 0.05f
// logit(0.05): sigmoid(x) > 0.05  <=>  x > LOGIT_THRESH
#define LOGIT_THRESH (-2.9444389791664403f)
#define FULLM 0xffffffffu

__device__ __forceinline__ float max3(float a, float b, float c) {
    return fmaxf(a, fmaxf(b, c));
}

__device__ __forceinline__ float4 max3v(const float4& a, const float4& b, const float4& c) {
    float4 r;
    r.x = max3(a.x, b.x, c.x);
    r.y = max3(a.y, b.y, c.y);
    r.z = max3(a.z, b.z, c.z);
    r.w = max3(a.w, b.w, c.w);
    return r;
}

// peak score: sigmoid(x) if (3x3 max == x) && x > logit(0.05), else 0
__device__ __forceinline__ float peak(float m, float x) {
    float e = __expf(-x);
    float s = __fdividef(1.0f, 1.0f + e);
    return (m == x && x > LOGIT_THRESH) ? s : 0.0f;
}

__device__ __forceinline__ float4 peaks4(const float4& c, const float4& v,
                                         float vl, float vr) {
    float4 r;
    r.x = peak(max3(vl,  v.x, v.y), c.x);
    r.y = peak(max3(v.x, v.y, v.z), c.y);
    r.z = peak(max3(v.y, v.z, v.w), c.z);
    r.w = peak(max3(v.z, v.w, vr),  c.w);
    return r;
}

__global__ __launch_bounds__(TPB, 11)
void heatmap_peaks_kernel(const float* __restrict__ in, float* __restrict__ out) {
    const int lane = threadIdx.x & 31;
    const int warp = threadIdx.x >> 5;
    const int unit = blockIdx.x * WARPS + warp;

    const int plane = unit / BANDS;
    const int band  = unit - plane * BANDS;

    const float* __restrict__ p = in  + (size_t)plane * (HM_W * HM_H);
    float* __restrict__       o = out + (size_t)plane * (HM_W * HM_H);

    const int r0 = band * BAND;
    const int xb = lane * 4;           // interleaved: cols xb, xb+128, xb+256
    const float NEG = -CUDART_INF_F;
    const float4 NEG4 = make_float4(NEG, NEG, NEG, NEG);

    // Carried rows P (prev), C (cur). 3 coalesced float4 chunks each.
    float4 P0, P1, P2, C0, C1, C2;

    if (r0 > 0) {
        const float* rp = p + (size_t)(r0 - 1) * HM_W + xb;
        P0 = *(const float4*)(rp);
        P1 = *(const float4*)(rp + 128);
        P2 = *(const float4*)(rp + 256);
    } else {
        P0 = NEG4; P1 = NEG4; P2 = NEG4;
    }
    {
        const float* rp = p + (size_t)r0 * HM_W + xb;
        C0 = *(const float4*)(rp);
        C1 = *(const float4*)(rp + 128);
        C2 = *(const float4*)(rp + 256);
    }

    const float* np = p + (size_t)(r0 + 1) * HM_W + xb;   // next-row pointer
    float*       op = o + (size_t)r0 * HM_W + xb;         // output-row pointer

    #pragma unroll 4
    for (int r = r0; r < r0 + BAND; ++r) {
        // Load next row (independent of compute below; ptxas batches across unroll)
        float4 N0, N1, N2;
        if (r + 1 < HM_H) {
            N0 = *(const float4*)(np);
            N1 = *(const float4*)(np + 128);
            N2 = *(const float4*)(np + 256);
        } else {
            N0 = NEG4; N1 = NEG4; N2 = NEG4;
        }
        np += HM_W;

        // Vertical 3-max per column
        float4 v0 = max3v(P0, C0, N0);
        float4 v1 = max3v(P1, C1, N1);
        float4 v2 = max3v(P2, C2, N2);

        // Horizontal neighbors via warp shuffles.
        float l0 = __shfl_up_sync(FULLM, v0.w, 1);
        float l1 = __shfl_up_sync(FULLM, v1.w, 1);
        float l2 = __shfl_up_sync(FULLM, v2.w, 1);
        float b01 = __shfl_sync(FULLM, v0.w, 31);
        float b12 = __shfl_sync(FULLM, v1.w, 31);
        float r0s = __shfl_down_sync(FULLM, v0.x, 1);
        float r1s = __shfl_down_sync(FULLM, v1.x, 1);
        float r2s = __shfl_down_sync(FULLM, v2.x, 1);
        float f10 = __shfl_sync(FULLM, v1.x, 0);
        float f21 = __shfl_sync(FULLM, v2.x, 0);

        if (lane == 0)  { l0 = NEG; l1 = b01; l2 = b12; }
        if (lane == 31) { r0s = f10; r1s = f21; r2s = NEG; }

        // Peak test + sigmoid, store row
        float4 o0 = peaks4(C0, v0, l0, r0s);
        float4 o1 = peaks4(C1, v1, l1, r1s);
        float4 o2 = peaks4(C2, v2, l2, r2s);

        *(float4*)(op)       = o0;
        *(float4*)(op + 128) = o1;
        *(float4*)(op + 256) = o2;
        op += HM_W;

        // Rotate carried rows
        P0 = C0; P1 = C1; P2 = C2;
        C0 = N0; C1 = N1; C2 = N2;
    }
}

extern "C" void kernel_launch(void* const* d_in, const int* in_sizes, int n_in,
                              void* d_out, int out_size) {
    (void)in_sizes; (void)n_in; (void)out_size;
    const float* heatmaps = (const float*)d_in[0];
    float* out = (float*)d_out;

    heatmap_peaks_kernel<<<NBLOCKS, TPB>>>(heatmaps, out);
}